// round 10
// baseline (speedup 1.0000x reference)
#include <cuda_runtime.h>
#include <cuda_fp16.h>
#include <stdint.h>

#define BS   8
#define SEQ  2048
#define DIN  512
#define DK   64
#define MTOT (BS * SEQ)
#define SPLIT 4
#define KEYS_PER_SPLIT (SEQ / SPLIT)            // 512
#define TILES_PER_SPLIT (KEYS_PER_SPLIT / 128)  // 4

// Projected Q/K/V in fp16. Q pre-scaled by log2(e)/sqrt(dk). 2 MB each.
__device__ __half g_q[MTOT * DK];
__device__ __half g_k[MTOT * DK];
__device__ __half g_v[MTOT * DK];
// Split-KV partials (unnormalized O and row sums l)
__device__ float g_op[SPLIT * MTOT * DK];   // 16 MB
__device__ float g_lp[SPLIT * MTOT];

#define QSCALE 0.18033688011112042f   // 0.125 * log2(e)

// ---------------------------------------------------------------------------
// helpers
// ---------------------------------------------------------------------------
__device__ __forceinline__ uint32_t smem_u32(const void* p) {
    uint32_t a;
    asm("{ .reg .u64 t; cvta.to.shared.u64 t, %1; cvt.u32.u64 %0, t; }" : "=r"(a) : "l"(p));
    return a;
}
__device__ __forceinline__ void cp16(uint32_t dst, const void* src) {
    asm volatile("cp.async.cg.shared.global [%0], [%1], 16;" :: "r"(dst), "l"(src) : "memory");
}
#define CP_COMMIT() asm volatile("cp.async.commit_group;" ::: "memory")
#define CP_WAIT(n)  asm volatile("cp.async.wait_group %0;" :: "n"(n) : "memory")

__device__ __forceinline__ uint32_t pack2(float lo, float hi) {
    uint32_t u;
    asm("cvt.rn.f16x2.f32 %0, %1, %2;" : "=r"(u) : "f"(hi), "f"(lo));
    return u;
}
__device__ __forceinline__ float ex2f(float x) {
    float y;
    asm("ex2.approx.ftz.f32 %0, %1;" : "=f"(y) : "f"(x));
    return y;
}

// D += A(16x16) * B(16x8)  fp16 in, f32 accum
__device__ __forceinline__ void hmma(float* d, const uint32_t* a, const uint32_t* b) {
    asm volatile(
        "mma.sync.aligned.m16n8k16.row.col.f32.f16.f16.f32 "
        "{%0,%1,%2,%3}, {%4,%5,%6,%7}, {%8,%9}, {%0,%1,%2,%3};"
        : "+f"(d[0]), "+f"(d[1]), "+f"(d[2]), "+f"(d[3])
        : "r"(a[0]), "r"(a[1]), "r"(a[2]), "r"(a[3]), "r"(b[0]), "r"(b[1]));
}

__device__ __forceinline__ void ldm4(uint32_t* r, uint32_t addr) {
    asm volatile("ldmatrix.sync.aligned.m8n8.x4.shared.b16 {%0,%1,%2,%3}, [%4];"
                 : "=r"(r[0]), "=r"(r[1]), "=r"(r[2]), "=r"(r[3]) : "r"(addr));
}
__device__ __forceinline__ void ldm4t(uint32_t* r, uint32_t addr) {
    asm volatile("ldmatrix.sync.aligned.m8n8.x4.trans.shared.b16 {%0,%1,%2,%3}, [%4];"
                 : "=r"(r[0]), "=r"(r[1]), "=r"(r[2]), "=r"(r[3]) : "r"(addr));
}

// ---------------------------------------------------------------------------
// Projection v3: cp.async 3-stage fp32 staging -> fp16 convert -> HMMA.
// grid (128, 3). 256 threads, warp = 16 rows x 64 cols.
// smem: W fp16 73728 | Xh fp16 18432 | 3 x fp32 stage 34816 = 196608 B.
// ---------------------------------------------------------------------------
#define WSTR 72
#define XFSTR 68                                   // fp32 staging stride (floats)
#define PROJ_W_B   (512 * WSTR * 2)                // 73728
#define XH_OFF     PROJ_W_B                        // fp16 X buffer
#define PROJ_XH_B  (128 * WSTR * 2)                // 18432
#define XS_OFF     (XH_OFF + PROJ_XH_B)            // fp32 stages
#define STAGE_B    (128 * XFSTR * 4)               // 34816
#define PROJ_SMEM  (XS_OFF + 3 * STAGE_B)          // 196608

__device__ __forceinline__ void proj_fill_stage(uint32_t sb, int s,
                                                const float* Xt, int tid) {
    uint32_t base = sb + XS_OFF + (uint32_t)s * STAGE_B;
    #pragma unroll
    for (int i = 0; i < 8; i++) {
        int id = tid + i * 256;
        int r = id >> 4, ch = id & 15;
        cp16(base + (uint32_t)(r * (XFSTR * 4) + ch * 16),
             Xt + (size_t)r * DIN + ch * 4);
    }
    CP_COMMIT();
}

__global__ __launch_bounds__(256, 1) void proj_h(
    const float* __restrict__ Xq, const float* __restrict__ Xk, const float* __restrict__ Xv,
    const float* __restrict__ Wq_, const float* __restrict__ bq_,
    const float* __restrict__ Wk_, const float* __restrict__ bk_,
    const float* __restrict__ Wv_, const float* __restrict__ bv_) {
    extern __shared__ __half psm[];
    const uint32_t sb = smem_u32(psm);
    const uint32_t Xhu = sb + XH_OFF;

    const int which = blockIdx.y;
    const float* X    = (which == 0) ? Xq  : (which == 1) ? Xk  : Xv;
    const float* W    = (which == 0) ? Wq_ : (which == 1) ? Wk_ : Wv_;
    const float* bias = (which == 0) ? bq_ : (which == 1) ? bk_ : bv_;
    __half* Y         = (which == 0) ? g_q : (which == 1) ? g_k : g_v;
    const float scale = (which == 0) ? QSCALE : 1.0f;

    const int tid = threadIdx.x, lane = tid & 31, wid = tid >> 5;
    const int g = lane >> 2, tig = lane & 3;
    const int lr = lane & 7, grp = lane >> 3;
    const int m0 = wid * 16;
    const int row0 = blockIdx.x * 128;
    const float* Xrow = X + (size_t)row0 * DIN;

    const int roffA = ((grp & 1) ? 8 : 0) + lr;
    const int coffA = (grp & 2) ? 8 : 0;
    const int roffB = ((grp & 1) ? 8 : 0) + lr;
    const int coffB = (grp & 2) ? 8 : 0;

    // prologue: stages 0..2 in flight
    proj_fill_stage(sb, 0, Xrow, tid);
    proj_fill_stage(sb, 1, Xrow + 64, tid);
    proj_fill_stage(sb, 2, Xrow + 128, tid);

    // ---- W -> smem fp16 (one-time, overlaps with cp.async) ----
    #pragma unroll
    for (int i = 0; i < 32; i++) {
        int id = tid + i * 256;
        int r = id >> 4, c4 = (id & 15) * 4;
        float4 x = *(const float4*)&W[(size_t)r * DK + c4];
        uint2 h;
        h.x = pack2(x.x, x.y); h.y = pack2(x.z, x.w);
        *(uint2*)(psm + r * WSTR + c4) = h;
    }

    float c[8][4] = {};

    #pragma unroll
    for (int t = 0; t < 8; t++) {
        // wait for stage t
        if (t < 6)      CP_WAIT(2);
        else if (t == 6) CP_WAIT(1);
        else             CP_WAIT(0);
        __syncthreads();   // stage visible to all; Xh free from previous MMA

        // convert fp32 stage -> fp16 Xh
        {
            const float* St = (const float*)(psm) +
                              (XS_OFF / 4) + (size_t)(t % 3) * (STAGE_B / 4);
            #pragma unroll
            for (int i = 0; i < 8; i++) {
                int id = tid + i * 256;
                int r = id >> 4, c4 = (id & 15) * 4;
                float4 x = *(const float4*)&St[r * XFSTR + c4];
                uint2 h;
                h.x = pack2(x.x, x.y); h.y = pack2(x.z, x.w);
                *(uint2*)(psm + (XH_OFF / 2) + r * WSTR + c4) = h;
            }
        }
        __syncthreads();   // Xh ready; stage t consumed by all threads

        // refill stage (t%3) with tile t+3 — overlaps with MMA below
        if (t + 3 < 8) proj_fill_stage(sb, t % 3, Xrow + (t + 3) * 64, tid);

        #pragma unroll
        for (int kc = 0; kc < 4; kc++) {
            uint32_t a[4];
            ldm4(a, Xhu + (uint32_t)((m0 + roffA) * WSTR + kc * 16 + coffA) * 2);
            #pragma unroll
            for (int n16 = 0; n16 < 4; n16++) {
                uint32_t bb[4];
                ldm4t(bb, sb + (uint32_t)((t * 64 + kc * 16 + roffB) * WSTR
                                          + n16 * 16 + coffB) * 2);
                hmma(c[2 * n16],     a, bb);
                hmma(c[2 * n16 + 1], a, bb + 2);
            }
        }
    }

    #pragma unroll
    for (int n = 0; n < 8; n++) {
        int col = 8 * n + 2 * tig;
        float b0 = bias[col], b1 = bias[col + 1];
        int r = row0 + m0 + g;
        __half2 h0 = __floats2half2_rn((c[n][0] + b0) * scale, (c[n][1] + b1) * scale);
        __half2 h1 = __floats2half2_rn((c[n][2] + b0) * scale, (c[n][3] + b1) * scale);
        *(__half2*)&Y[(size_t)r * DK + col] = h0;
        *(__half2*)&Y[(size_t)(r + 8) * DK + col] = h1;
    }
}

// ---------------------------------------------------------------------------
// Attention v8: split-KV x4 across grid.z. grid (32, 8, 4) = 1024 CTAs.
// Each CTA: 64 q-rows x 512 keys (4 tiles of 128, double-buffered).
// ---------------------------------------------------------------------------
#define VSTR  72
#define VSTR2 (VSTR * 2)
#define TILEB (128 * VSTR2)
#define BUFB  (2 * TILEB)
#define ATTN_SMEM (2 * BUFB)              // 73728

__device__ __forceinline__ void load_tile(uint32_t sb, int buf,
                                          const __half* kp, const __half* vp, int tid) {
    uint32_t kaddr = sb + (uint32_t)buf * BUFB;
    uint32_t vaddr = kaddr + TILEB;
    #pragma unroll
    for (int i = 0; i < 8; i++) {
        int id = tid + i * 128;
        int r = id >> 3, ch = id & 7;
        uint32_t off = (uint32_t)(r * VSTR2 + ch * 16);
        cp16(kaddr + off, kp + (size_t)r * DK + ch * 8);
        cp16(vaddr + off, vp + (size_t)r * DK + ch * 8);
    }
    CP_COMMIT();
}

__global__ __launch_bounds__(128, 3) void attn_h() {
    extern __shared__ __half smh[];
    const uint32_t sb = smem_u32(smh);

    const int tid = threadIdx.x, lane = tid & 31, wid = tid >> 5;
    const int g = lane >> 2, tig = lane & 3;
    const int lr = lane & 7, grp = lane >> 3;
    const int m0 = wid * 16;
    const int b = blockIdx.y, qt = blockIdx.x, z = blockIdx.z;
    const size_t qbase = ((size_t)b * SEQ + (size_t)qt * 64) * DK;
    const size_t kvbase = ((size_t)b * SEQ + (size_t)z * KEYS_PER_SPLIT) * DK;

    float* op = g_op + (size_t)z * MTOT * DK;
    float* lp = g_lp + (size_t)z * MTOT;

    const int roff1 = ((grp & 2) ? 8 : 0) + lr;   // K, non-trans
    const int coff1 = (grp & 1) * 16;
    const int roff2 = ((grp & 1) ? 8 : 0) + lr;   // V, trans
    const int coff2 = (grp & 2) ? 16 : 0;

    // ---- Q fragments (pre-scaled by 0.125*log2e in proj) ----
    uint32_t qa[4][4];
    {
        const __half* qp = g_q + qbase;
        const int rA = (m0 + g) * DK, rB = (m0 + 8 + g) * DK;
        #pragma unroll
        for (int s4 = 0; s4 < 4; s4++) {
            qa[s4][0] = *(const uint32_t*)(qp + rA + 16 * s4 + 2 * tig);
            qa[s4][1] = *(const uint32_t*)(qp + rB + 16 * s4 + 2 * tig);
            qa[s4][2] = *(const uint32_t*)(qp + rA + 16 * s4 + 8 + 2 * tig);
            qa[s4][3] = *(const uint32_t*)(qp + rB + 16 * s4 + 8 + 2 * tig);
        }
    }

    load_tile(sb, 0, g_k + kvbase, g_v + kvbase, tid);

    float o[8][4] = {};
    float l_lo = 0.f, l_hi = 0.f;

    for (int t = 0; t < TILES_PER_SPLIT; t++) {
        if (t + 1 < TILES_PER_SPLIT) {
            const size_t nb = kvbase + (size_t)(t + 1) * 128 * DK;
            load_tile(sb, (t + 1) & 1, g_k + nb, g_v + nb, tid);
            CP_WAIT(1);
        } else {
            CP_WAIT(0);
        }
        __syncthreads();

        const uint32_t Kb = sb + (uint32_t)(t & 1) * BUFB;
        const uint32_t Vb = Kb + TILEB;

        #pragma unroll
        for (int h = 0; h < 2; h++) {           // 64-key halves (low regs)
            const uint32_t Kh = Kb + (uint32_t)h * 64 * VSTR2;
            const uint32_t Vh = Vb + (uint32_t)h * 64 * VSTR2;

            float s[8][4] = {};
            #pragma unroll
            for (int s4 = 0; s4 < 4; s4++) {
                #pragma unroll
                for (int j2 = 0; j2 < 4; j2++) {
                    uint32_t bb[4];
                    ldm4(bb, Kh + (uint32_t)((16 * j2 + roff1) * VSTR2 + 32 * s4 + coff1));
                    hmma(s[2 * j2],     qa[s4], bb);
                    hmma(s[2 * j2 + 1], qa[s4], bb + 2);
                }
            }

            float rlo = 0.f, rhi = 0.f;
            #pragma unroll
            for (int j = 0; j < 8; j++) {
                float e0 = ex2f(s[j][0]); float e1 = ex2f(s[j][1]);
                float e2 = ex2f(s[j][2]); float e3 = ex2f(s[j][3]);
                rlo += e0 + e1; rhi += e2 + e3;
                s[j][0] = e0; s[j][1] = e1; s[j][2] = e2; s[j][3] = e3;
            }
            l_lo += rlo; l_hi += rhi;

            #pragma unroll
            for (int s2 = 0; s2 < 4; s2++) {
                uint32_t a[4];
                a[0] = pack2(s[2 * s2][0],     s[2 * s2][1]);
                a[1] = pack2(s[2 * s2][2],     s[2 * s2][3]);
                a[2] = pack2(s[2 * s2 + 1][0], s[2 * s2 + 1][1]);
                a[3] = pack2(s[2 * s2 + 1][2], s[2 * s2 + 1][3]);
                #pragma unroll
                for (int j2 = 0; j2 < 4; j2++) {
                    uint32_t bb[4];
                    ldm4t(bb, Vh + (uint32_t)((16 * s2 + roff2) * VSTR2 + 32 * j2 + coff2));
                    hmma(o[2 * j2],     a, bb);
                    hmma(o[2 * j2 + 1], a, bb + 2);
                }
            }
        }
        __syncthreads();
    }

    l_lo += __shfl_xor_sync(0xffffffffu, l_lo, 1);
    l_lo += __shfl_xor_sync(0xffffffffu, l_lo, 2);
    l_hi += __shfl_xor_sync(0xffffffffu, l_hi, 1);
    l_hi += __shfl_xor_sync(0xffffffffu, l_hi, 2);

    const size_t obase = qbase;
    if (tig == 0) {
        lp[(size_t)b * SEQ + qt * 64 + m0 + g] = l_lo;
        lp[(size_t)b * SEQ + qt * 64 + m0 + 8 + g] = l_hi;
    }
    #pragma unroll
    for (int n = 0; n < 8; n++) {
        int col = 8 * n + 2 * tig;
        *(float2*)&op[obase + (size_t)(m0 + g) * DK + col] =
            make_float2(o[n][0], o[n][1]);
        *(float2*)&op[obase + (size_t)(m0 + 8 + g) * DK + col] =
            make_float2(o[n][2], o[n][3]);
    }
}

// ---------------------------------------------------------------------------
// Reduce: out = sum_z op_z / sum_z l_z, float4-vectorized.
// ---------------------------------------------------------------------------
__global__ __launch_bounds__(256) void reduce_k(float* __restrict__ O) {
    int idx = blockIdx.x * 256 + threadIdx.x;   // over MTOT*16 float4s
    int row = idx >> 4;
    float l = 0.f;
    #pragma unroll
    for (int z = 0; z < SPLIT; z++) l += g_lp[(size_t)z * MTOT + row];
    float inv = 1.0f / l;
    float4 acc = ((const float4*)g_op)[idx];
    #pragma unroll
    for (int z = 1; z < SPLIT; z++) {
        float4 p = ((const float4*)g_op)[(size_t)z * (MTOT * DK / 4) + idx];
        acc.x += p.x; acc.y += p.y; acc.z += p.z; acc.w += p.w;
    }
    acc.x *= inv; acc.y *= inv; acc.z *= inv; acc.w *= inv;
    ((float4*)O)[idx] = acc;
}

// ---------------------------------------------------------------------------
extern "C" void kernel_launch(void* const* d_in, const int* in_sizes, int n_in,
                              void* d_out, int out_size) {
    const float* q_in = (const float*)d_in[0];
    const float* k_in = (const float*)d_in[1];
    const float* v_in = (const float*)d_in[2];
    const float* Wq   = (const float*)d_in[3];
    const float* bq   = (const float*)d_in[4];
    const float* Wk   = (const float*)d_in[5];
    const float* bk   = (const float*)d_in[6];
    const float* Wv   = (const float*)d_in[7];
    const float* bv   = (const float*)d_in[8];
    float* out = (float*)d_out;

    cudaFuncSetAttribute(proj_h, cudaFuncAttributeMaxDynamicSharedMemorySize, PROJ_SMEM);
    dim3 pgrid(MTOT / 128, 3);        // (128, 3)
    proj_h<<<pgrid, 256, PROJ_SMEM>>>(q_in, k_in, v_in, Wq, bq, Wk, bk, Wv, bv);

    cudaFuncSetAttribute(attn_h, cudaFuncAttributeMaxDynamicSharedMemorySize, ATTN_SMEM);
    dim3 agrid(SEQ / 64, BS, SPLIT);  // (32, 8, 4)
    attn_h<<<agrid, 128, ATTN_SMEM>>>();

    reduce_k<<<(MTOT * 16) / 256, 256>>>(out);
}

// round 12
// speedup vs baseline: 1.0042x; 1.0042x over previous
#include <cuda_runtime.h>
#include <cuda_fp16.h>
#include <stdint.h>

#define BS   8
#define SEQ  2048
#define DIN  512
#define DK   64
#define MTOT (BS * SEQ)
#define SPLIT 4
#define KEYS_PER_SPLIT (SEQ / SPLIT)            // 512
#define TILES_PER_SPLIT (KEYS_PER_SPLIT / 128)  // 4

// Projected Q/K/V in fp16. Q pre-scaled by log2(e)/sqrt(dk). 2 MB each.
__device__ __half g_q[MTOT * DK];
__device__ __half g_k[MTOT * DK];
__device__ __half g_v[MTOT * DK];
// Split-KV partials (unnormalized O and row sums l)
__device__ float g_op[SPLIT * MTOT * DK];   // 16 MB
__device__ float g_lp[SPLIT * MTOT];

#define QSCALE 0.18033688011112042f   // 0.125 * log2(e)

// ---------------------------------------------------------------------------
// helpers
// ---------------------------------------------------------------------------
__device__ __forceinline__ uint32_t smem_u32(const void* p) {
    uint32_t a;
    asm("{ .reg .u64 t; cvta.to.shared.u64 t, %1; cvt.u32.u64 %0, t; }" : "=r"(a) : "l"(p));
    return a;
}
__device__ __forceinline__ void cp16(uint32_t dst, const void* src) {
    asm volatile("cp.async.cg.shared.global [%0], [%1], 16;" :: "r"(dst), "l"(src) : "memory");
}
#define CP_COMMIT() asm volatile("cp.async.commit_group;" ::: "memory")
#define CP_WAIT(n)  asm volatile("cp.async.wait_group %0;" :: "n"(n) : "memory")

__device__ __forceinline__ uint32_t pack2(float lo, float hi) {
    uint32_t u;
    asm("cvt.rn.f16x2.f32 %0, %1, %2;" : "=r"(u) : "f"(hi), "f"(lo));
    return u;
}
__device__ __forceinline__ float ex2f(float x) {
    float y;
    asm("ex2.approx.ftz.f32 %0, %1;" : "=f"(y) : "f"(x));
    return y;
}

// D += A(16x16) * B(16x8)  fp16 in, f32 accum
__device__ __forceinline__ void hmma(float* d, const uint32_t* a, const uint32_t* b) {
    asm volatile(
        "mma.sync.aligned.m16n8k16.row.col.f32.f16.f16.f32 "
        "{%0,%1,%2,%3}, {%4,%5,%6,%7}, {%8,%9}, {%0,%1,%2,%3};"
        : "+f"(d[0]), "+f"(d[1]), "+f"(d[2]), "+f"(d[3])
        : "r"(a[0]), "r"(a[1]), "r"(a[2]), "r"(a[3]), "r"(b[0]), "r"(b[1]));
}

__device__ __forceinline__ void ldm4(uint32_t* r, uint32_t addr) {
    asm volatile("ldmatrix.sync.aligned.m8n8.x4.shared.b16 {%0,%1,%2,%3}, [%4];"
                 : "=r"(r[0]), "=r"(r[1]), "=r"(r[2]), "=r"(r[3]) : "r"(addr));
}
__device__ __forceinline__ void ldm4t(uint32_t* r, uint32_t addr) {
    asm volatile("ldmatrix.sync.aligned.m8n8.x4.trans.shared.b16 {%0,%1,%2,%3}, [%4];"
                 : "=r"(r[0]), "=r"(r[1]), "=r"(r[2]), "=r"(r[3]) : "r"(addr));
}

// ---------------------------------------------------------------------------
// Projection v3: cp.async 3-stage fp32 staging -> fp16 convert -> HMMA.
// grid (128, 3). 256 threads, warp = 16 rows x 64 cols.
// smem: W fp16 73728 | Xh fp16 18432 | 3 x fp32 stage 34816 = 196608 B.
// ---------------------------------------------------------------------------
#define WSTR 72
#define XFSTR 68                                   // fp32 staging stride (floats)
#define PROJ_W_B   (512 * WSTR * 2)                // 73728
#define XH_OFF     PROJ_W_B                        // fp16 X buffer
#define PROJ_XH_B  (128 * WSTR * 2)                // 18432
#define XS_OFF     (XH_OFF + PROJ_XH_B)            // fp32 stages
#define STAGE_B    (128 * XFSTR * 4)               // 34816
#define PROJ_SMEM  (XS_OFF + 3 * STAGE_B)          // 196608

__device__ __forceinline__ void proj_fill_stage(uint32_t sb, int s,
                                                const float* Xt, int tid) {
    uint32_t base = sb + XS_OFF + (uint32_t)s * STAGE_B;
    #pragma unroll
    for (int i = 0; i < 8; i++) {
        int id = tid + i * 256;
        int r = id >> 4, ch = id & 15;
        cp16(base + (uint32_t)(r * (XFSTR * 4) + ch * 16),
             Xt + (size_t)r * DIN + ch * 4);
    }
    CP_COMMIT();
}

__global__ __launch_bounds__(256, 1) void proj_h(
    const float* __restrict__ Xq, const float* __restrict__ Xk, const float* __restrict__ Xv,
    const float* __restrict__ Wq_, const float* __restrict__ bq_,
    const float* __restrict__ Wk_, const float* __restrict__ bk_,
    const float* __restrict__ Wv_, const float* __restrict__ bv_) {
    extern __shared__ __half psm[];
    const uint32_t sb = smem_u32(psm);
    const uint32_t Xhu = sb + XH_OFF;

    const int which = blockIdx.y;
    const float* X    = (which == 0) ? Xq  : (which == 1) ? Xk  : Xv;
    const float* W    = (which == 0) ? Wq_ : (which == 1) ? Wk_ : Wv_;
    const float* bias = (which == 0) ? bq_ : (which == 1) ? bk_ : bv_;
    __half* Y         = (which == 0) ? g_q : (which == 1) ? g_k : g_v;
    const float scale = (which == 0) ? QSCALE : 1.0f;

    const int tid = threadIdx.x, lane = tid & 31, wid = tid >> 5;
    const int g = lane >> 2, tig = lane & 3;
    const int lr = lane & 7, grp = lane >> 3;
    const int m0 = wid * 16;
    const int row0 = blockIdx.x * 128;
    const float* Xrow = X + (size_t)row0 * DIN;

    const int roffA = ((grp & 1) ? 8 : 0) + lr;
    const int coffA = (grp & 2) ? 8 : 0;
    const int roffB = ((grp & 1) ? 8 : 0) + lr;
    const int coffB = (grp & 2) ? 8 : 0;

    // prologue: stages 0..2 in flight
    proj_fill_stage(sb, 0, Xrow, tid);
    proj_fill_stage(sb, 1, Xrow + 64, tid);
    proj_fill_stage(sb, 2, Xrow + 128, tid);

    // ---- W -> smem fp16 (one-time, overlaps with cp.async) ----
    #pragma unroll
    for (int i = 0; i < 32; i++) {
        int id = tid + i * 256;
        int r = id >> 4, c4 = (id & 15) * 4;
        float4 x = *(const float4*)&W[(size_t)r * DK + c4];
        uint2 h;
        h.x = pack2(x.x, x.y); h.y = pack2(x.z, x.w);
        *(uint2*)(psm + r * WSTR + c4) = h;
    }

    float c[8][4] = {};

    #pragma unroll
    for (int t = 0; t < 8; t++) {
        // wait for stage t
        if (t < 6)      CP_WAIT(2);
        else if (t == 6) CP_WAIT(1);
        else             CP_WAIT(0);
        __syncthreads();   // stage visible to all; Xh free from previous MMA

        // convert fp32 stage -> fp16 Xh
        {
            const float* St = (const float*)(psm) +
                              (XS_OFF / 4) + (size_t)(t % 3) * (STAGE_B / 4);
            #pragma unroll
            for (int i = 0; i < 8; i++) {
                int id = tid + i * 256;
                int r = id >> 4, c4 = (id & 15) * 4;
                float4 x = *(const float4*)&St[r * XFSTR + c4];
                uint2 h;
                h.x = pack2(x.x, x.y); h.y = pack2(x.z, x.w);
                *(uint2*)(psm + (XH_OFF / 2) + r * WSTR + c4) = h;
            }
        }
        __syncthreads();   // Xh ready; stage t consumed by all threads

        // refill stage (t%3) with tile t+3 — overlaps with MMA below
        if (t + 3 < 8) proj_fill_stage(sb, t % 3, Xrow + (t + 3) * 64, tid);

        #pragma unroll
        for (int kc = 0; kc < 4; kc++) {
            uint32_t a[4];
            ldm4(a, Xhu + (uint32_t)((m0 + roffA) * WSTR + kc * 16 + coffA) * 2);
            #pragma unroll
            for (int n16 = 0; n16 < 4; n16++) {
                uint32_t bb[4];
                ldm4t(bb, sb + (uint32_t)((t * 64 + kc * 16 + roffB) * WSTR
                                          + n16 * 16 + coffB) * 2);
                hmma(c[2 * n16],     a, bb);
                hmma(c[2 * n16 + 1], a, bb + 2);
            }
        }
    }

    #pragma unroll
    for (int n = 0; n < 8; n++) {
        int col = 8 * n + 2 * tig;
        float b0 = bias[col], b1 = bias[col + 1];
        int r = row0 + m0 + g;
        __half2 h0 = __floats2half2_rn((c[n][0] + b0) * scale, (c[n][1] + b1) * scale);
        __half2 h1 = __floats2half2_rn((c[n][2] + b0) * scale, (c[n][3] + b1) * scale);
        *(__half2*)&Y[(size_t)r * DK + col] = h0;
        *(__half2*)&Y[(size_t)(r + 8) * DK + col] = h1;
    }
}

// ---------------------------------------------------------------------------
// Attention v8: split-KV x4 across grid.z. grid (32, 8, 4) = 1024 CTAs.
// Each CTA: 64 q-rows x 512 keys (4 tiles of 128, double-buffered).
// ---------------------------------------------------------------------------
#define VSTR  72
#define VSTR2 (VSTR * 2)
#define TILEB (128 * VSTR2)
#define BUFB  (2 * TILEB)
#define ATTN_SMEM (2 * BUFB)              // 73728

__device__ __forceinline__ void load_tile(uint32_t sb, int buf,
                                          const __half* kp, const __half* vp, int tid) {
    uint32_t kaddr = sb + (uint32_t)buf * BUFB;
    uint32_t vaddr = kaddr + TILEB;
    #pragma unroll
    for (int i = 0; i < 8; i++) {
        int id = tid + i * 128;
        int r = id >> 3, ch = id & 7;
        uint32_t off = (uint32_t)(r * VSTR2 + ch * 16);
        cp16(kaddr + off, kp + (size_t)r * DK + ch * 8);
        cp16(vaddr + off, vp + (size_t)r * DK + ch * 8);
    }
    CP_COMMIT();
}

__global__ __launch_bounds__(128, 3) void attn_h() {
    extern __shared__ __half smh[];
    const uint32_t sb = smem_u32(smh);

    const int tid = threadIdx.x, lane = tid & 31, wid = tid >> 5;
    const int g = lane >> 2, tig = lane & 3;
    const int lr = lane & 7, grp = lane >> 3;
    const int m0 = wid * 16;
    const int b = blockIdx.y, qt = blockIdx.x, z = blockIdx.z;
    const size_t qbase = ((size_t)b * SEQ + (size_t)qt * 64) * DK;
    const size_t kvbase = ((size_t)b * SEQ + (size_t)z * KEYS_PER_SPLIT) * DK;

    float* op = g_op + (size_t)z * MTOT * DK;
    float* lp = g_lp + (size_t)z * MTOT;

    const int roff1 = ((grp & 2) ? 8 : 0) + lr;   // K, non-trans
    const int coff1 = (grp & 1) * 16;
    const int roff2 = ((grp & 1) ? 8 : 0) + lr;   // V, trans
    const int coff2 = (grp & 2) ? 16 : 0;

    // ---- Q fragments (pre-scaled by 0.125*log2e in proj) ----
    uint32_t qa[4][4];
    {
        const __half* qp = g_q + qbase;
        const int rA = (m0 + g) * DK, rB = (m0 + 8 + g) * DK;
        #pragma unroll
        for (int s4 = 0; s4 < 4; s4++) {
            qa[s4][0] = *(const uint32_t*)(qp + rA + 16 * s4 + 2 * tig);
            qa[s4][1] = *(const uint32_t*)(qp + rB + 16 * s4 + 2 * tig);
            qa[s4][2] = *(const uint32_t*)(qp + rA + 16 * s4 + 8 + 2 * tig);
            qa[s4][3] = *(const uint32_t*)(qp + rB + 16 * s4 + 8 + 2 * tig);
        }
    }

    load_tile(sb, 0, g_k + kvbase, g_v + kvbase, tid);

    float o[8][4] = {};
    float l_lo = 0.f, l_hi = 0.f;

    for (int t = 0; t < TILES_PER_SPLIT; t++) {
        if (t + 1 < TILES_PER_SPLIT) {
            const size_t nb = kvbase + (size_t)(t + 1) * 128 * DK;
            load_tile(sb, (t + 1) & 1, g_k + nb, g_v + nb, tid);
            CP_WAIT(1);
        } else {
            CP_WAIT(0);
        }
        __syncthreads();

        const uint32_t Kb = sb + (uint32_t)(t & 1) * BUFB;
        const uint32_t Vb = Kb + TILEB;

        #pragma unroll
        for (int h = 0; h < 2; h++) {           // 64-key halves (low regs)
            const uint32_t Kh = Kb + (uint32_t)h * 64 * VSTR2;
            const uint32_t Vh = Vb + (uint32_t)h * 64 * VSTR2;

            float s[8][4] = {};
            #pragma unroll
            for (int s4 = 0; s4 < 4; s4++) {
                #pragma unroll
                for (int j2 = 0; j2 < 4; j2++) {
                    uint32_t bb[4];
                    ldm4(bb, Kh + (uint32_t)((16 * j2 + roff1) * VSTR2 + 32 * s4 + coff1));
                    hmma(s[2 * j2],     qa[s4], bb);
                    hmma(s[2 * j2 + 1], qa[s4], bb + 2);
                }
            }

            float rlo = 0.f, rhi = 0.f;
            #pragma unroll
            for (int j = 0; j < 8; j++) {
                float e0 = ex2f(s[j][0]); float e1 = ex2f(s[j][1]);
                float e2 = ex2f(s[j][2]); float e3 = ex2f(s[j][3]);
                rlo += e0 + e1; rhi += e2 + e3;
                s[j][0] = e0; s[j][1] = e1; s[j][2] = e2; s[j][3] = e3;
            }
            l_lo += rlo; l_hi += rhi;

            #pragma unroll
            for (int s2 = 0; s2 < 4; s2++) {
                uint32_t a[4];
                a[0] = pack2(s[2 * s2][0],     s[2 * s2][1]);
                a[1] = pack2(s[2 * s2][2],     s[2 * s2][3]);
                a[2] = pack2(s[2 * s2 + 1][0], s[2 * s2 + 1][1]);
                a[3] = pack2(s[2 * s2 + 1][2], s[2 * s2 + 1][3]);
                #pragma unroll
                for (int j2 = 0; j2 < 4; j2++) {
                    uint32_t bb[4];
                    ldm4t(bb, Vh + (uint32_t)((16 * s2 + roff2) * VSTR2 + 32 * j2 + coff2));
                    hmma(o[2 * j2],     a, bb);
                    hmma(o[2 * j2 + 1], a, bb + 2);
                }
            }
        }
        __syncthreads();
    }

    l_lo += __shfl_xor_sync(0xffffffffu, l_lo, 1);
    l_lo += __shfl_xor_sync(0xffffffffu, l_lo, 2);
    l_hi += __shfl_xor_sync(0xffffffffu, l_hi, 1);
    l_hi += __shfl_xor_sync(0xffffffffu, l_hi, 2);

    const size_t obase = qbase;
    if (tig == 0) {
        lp[(size_t)b * SEQ + qt * 64 + m0 + g] = l_lo;
        lp[(size_t)b * SEQ + qt * 64 + m0 + 8 + g] = l_hi;
    }
    #pragma unroll
    for (int n = 0; n < 8; n++) {
        int col = 8 * n + 2 * tig;
        *(float2*)&op[obase + (size_t)(m0 + g) * DK + col] =
            make_float2(o[n][0], o[n][1]);
        *(float2*)&op[obase + (size_t)(m0 + 8 + g) * DK + col] =
            make_float2(o[n][2], o[n][3]);
    }
}

// ---------------------------------------------------------------------------
// Reduce: out = sum_z op_z / sum_z l_z, float4-vectorized.
// ---------------------------------------------------------------------------
__global__ __launch_bounds__(256) void reduce_k(float* __restrict__ O) {
    int idx = blockIdx.x * 256 + threadIdx.x;   // over MTOT*16 float4s
    int row = idx >> 4;
    float l = 0.f;
    #pragma unroll
    for (int z = 0; z < SPLIT; z++) l += g_lp[(size_t)z * MTOT + row];
    float inv = 1.0f / l;
    float4 acc = ((const float4*)g_op)[idx];
    #pragma unroll
    for (int z = 1; z < SPLIT; z++) {
        float4 p = ((const float4*)g_op)[(size_t)z * (MTOT * DK / 4) + idx];
        acc.x += p.x; acc.y += p.y; acc.z += p.z; acc.w += p.w;
    }
    acc.x *= inv; acc.y *= inv; acc.z *= inv; acc.w *= inv;
    ((float4*)O)[idx] = acc;
}

// ---------------------------------------------------------------------------
extern "C" void kernel_launch(void* const* d_in, const int* in_sizes, int n_in,
                              void* d_out, int out_size) {
    const float* q_in = (const float*)d_in[0];
    const float* k_in = (const float*)d_in[1];
    const float* v_in = (const float*)d_in[2];
    const float* Wq   = (const float*)d_in[3];
    const float* bq   = (const float*)d_in[4];
    const float* Wk   = (const float*)d_in[5];
    const float* bk   = (const float*)d_in[6];
    const float* Wv   = (const float*)d_in[7];
    const float* bv   = (const float*)d_in[8];
    float* out = (float*)d_out;

    cudaFuncSetAttribute(proj_h, cudaFuncAttributeMaxDynamicSharedMemorySize, PROJ_SMEM);
    dim3 pgrid(MTOT / 128, 3);        // (128, 3)
    proj_h<<<pgrid, 256, PROJ_SMEM>>>(q_in, k_in, v_in, Wq, bq, Wk, bk, Wv, bv);

    cudaFuncSetAttribute(attn_h, cudaFuncAttributeMaxDynamicSharedMemorySize, ATTN_SMEM);
    dim3 agrid(SEQ / 64, BS, SPLIT);  // (32, 8, 4)
    attn_h<<<agrid, 128, ATTN_SMEM>>>();

    reduce_k<<<(MTOT * 16) / 256, 256>>>(out);
}